// round 1
// baseline (speedup 1.0000x reference)
#include <cuda_runtime.h>
#include <cuda_bf16.h>
#include <cstdint>

// NT-Xent loss: B=8,S=512,D=128 -> N=4096 rows per half, 2N=8192 total rows.
// loss = mean_i( lse_i - pos_i ),  lse_i = log sum_{j!=i} exp(<z_i,z_j>/T),
// pos_i = <zi_k, zj_k>/T for i = k or k+N.
//
// Pipeline:
//   k1: normalize rows (fp32), convert to bf16, zero rowsum
//   k2: bf16 mma.sync GEMM of Z·Z^T tiles; exp via MUFU; accumulate row sums
//   k3: pos dots
//   k4: finalize (log + mean) -> out[0]

#define NTOT 8192
#define HALF_N 4096
#define DDIM 128
#define PAD 136          // halves per smem row (272B stride: conflict-free ldmatrix)
#define SCALE_EX2 20.6099291555566218f   // log2(e)/0.07
#define INV_T (1.0f/0.07f)

__device__ __nv_bfloat16 g_Zb[NTOT * DDIM];
__device__ float g_rowsum[NTOT];
__device__ float g_posv[HALF_N];

// ---------------------------------------------------------------- utilities
__device__ __forceinline__ float fexp2(float x) {
    float y;
    asm("ex2.approx.f32 %0, %1;" : "=f"(y) : "f"(x));
    return y;
}

__device__ __forceinline__ void ldmatrix_x4(uint32_t* r, const void* p) {
    uint32_t sa = (uint32_t)__cvta_generic_to_shared(p);
    asm volatile("ldmatrix.sync.aligned.m8n8.x4.shared.b16 {%0,%1,%2,%3}, [%4];"
                 : "=r"(r[0]), "=r"(r[1]), "=r"(r[2]), "=r"(r[3]) : "r"(sa));
}

__device__ __forceinline__ void mma16816(float* d, const uint32_t* a,
                                          uint32_t b0, uint32_t b1) {
    asm volatile(
        "mma.sync.aligned.m16n8k16.row.col.f32.bf16.bf16.f32 "
        "{%0,%1,%2,%3}, {%4,%5,%6,%7}, {%8,%9}, {%0,%1,%2,%3};"
        : "+f"(d[0]), "+f"(d[1]), "+f"(d[2]), "+f"(d[3])
        : "r"(a[0]), "r"(a[1]), "r"(a[2]), "r"(a[3]), "r"(b0), "r"(b1));
}

// ---------------------------------------------------------------- kernel 1
// One warp per row: fp32 normalize -> bf16, zero rowsum.
__global__ __launch_bounds__(256) void norm_kernel(const float* __restrict__ zi,
                                                   const float* __restrict__ zj) {
    int warpId = threadIdx.x >> 5;
    int lane = threadIdx.x & 31;
    int row = blockIdx.x * 8 + warpId;
    const float* src = (row < HALF_N) ? (zi + (size_t)row * DDIM)
                                      : (zj + (size_t)(row - HALF_N) * DDIM);
    float4 v = ((const float4*)src)[lane];
    float ss = v.x * v.x + v.y * v.y + v.z * v.z + v.w * v.w;
#pragma unroll
    for (int off = 16; off > 0; off >>= 1)
        ss += __shfl_xor_sync(0xffffffffu, ss, off);
    float s = rsqrtf(fmaxf(ss, 1e-24f));
    __nv_bfloat162 h0 = __floats2bfloat162_rn(v.x * s, v.y * s);
    __nv_bfloat162 h1 = __floats2bfloat162_rn(v.z * s, v.w * s);
    __nv_bfloat162* dst = (__nv_bfloat162*)(g_Zb + (size_t)row * DDIM);
    dst[lane * 2 + 0] = h0;
    dst[lane * 2 + 1] = h1;
    if (lane == 0) g_rowsum[row] = 0.0f;
}

// ---------------------------------------------------------------- kernel 2
// Block tile 128(M) x 128(N), K=128. 256 threads = 8 warps (4 M x 2 N).
// A fragments live in registers for the whole block; B streamed via one
// 34KB smem buffer. Epilogue: exp2(sim*SCALE) via MUFU, diag masked,
// row-sum reduced in-warp, atomicAdd to g_rowsum.
__global__ __launch_bounds__(256) void simlse_kernel() {
    __shared__ __align__(16) __nv_bfloat16 sT[128 * PAD];

    int tid = threadIdx.x;
    int lane = tid & 31;
    int warpId = tid >> 5;
    int warpM = warpId & 3;   // 0..3
    int warpN = warpId >> 2;  // 0..1
    int mBase = warpM * 32;
    int nBase = warpN * 64;
    int rowBase = blockIdx.x * 128;

    // ---- load A tile (rows rowBase..+127) into smem, coalesced int4
    {
        const int4* src = (const int4*)(g_Zb + (size_t)rowBase * DDIM);
#pragma unroll
        for (int i = 0; i < 8; i++) {
            int idx = i * 256 + tid;
            int r = idx >> 4, c = idx & 15;
            *(int4*)(&sT[r * PAD + c * 8]) = src[r * 16 + c];
        }
    }
    __syncthreads();

    // ---- A fragments -> registers (8 k-steps x 2 m-atoms x 4 regs)
    uint32_t aF[8][2][4];
#pragma unroll
    for (int ks = 0; ks < 8; ks++)
#pragma unroll
        for (int am = 0; am < 2; am++) {
            const __nv_bfloat16* p =
                &sT[(mBase + am * 16 + (lane & 15)) * PAD + ks * 16 + (lane >> 4) * 8];
            ldmatrix_x4(aF[ks][am], p);
        }
    __syncthreads();

    float rowAcc[2][2] = {{0.f, 0.f}, {0.f, 0.f}};

    for (int ct = 0; ct < 8; ct++) {
        int colBase = blockIdx.y * 1024 + ct * 128;
        // ---- load B tile (rows colBase..+127) into smem
        {
            const int4* src = (const int4*)(g_Zb + (size_t)colBase * DDIM);
#pragma unroll
            for (int i = 0; i < 8; i++) {
                int idx = i * 256 + tid;
                int r = idx >> 4, c = idx & 15;
                *(int4*)(&sT[r * PAD + c * 8]) = src[r * 16 + c];
            }
        }
        __syncthreads();

        float acc[2][8][4];
#pragma unroll
        for (int am = 0; am < 2; am++)
#pragma unroll
            for (int an = 0; an < 8; an++)
#pragma unroll
                for (int v = 0; v < 4; v++) acc[am][an][v] = 0.0f;

#pragma unroll
        for (int ks = 0; ks < 8; ks++) {
            uint32_t bF[4][4];
#pragma unroll
            for (int bn = 0; bn < 4; bn++) {
                const __nv_bfloat16* p =
                    &sT[(nBase + bn * 16 + (lane & 15)) * PAD + ks * 16 + (lane >> 4) * 8];
                ldmatrix_x4(bF[bn], p);
            }
#pragma unroll
            for (int am = 0; am < 2; am++)
#pragma unroll
                for (int an = 0; an < 8; an++) {
                    uint32_t b0 = bF[an >> 1][(an & 1)];
                    uint32_t b1 = bF[an >> 1][2 + (an & 1)];
                    mma16816(acc[am][an], aF[ks][am], b0, b1);
                }
        }

        // ---- epilogue: exp + row accumulate (diag masked)
        bool diag = (rowBase == colBase);
#pragma unroll
        for (int am = 0; am < 2; am++)
#pragma unroll
            for (int an = 0; an < 8; an++)
#pragma unroll
                for (int v = 0; v < 4; v++) {
                    float e = fexp2(acc[am][an][v] * SCALE_EX2);
                    if (diag) {
                        int rl = mBase + am * 16 + (lane >> 2) + ((v >> 1) << 3);
                        int cl = nBase + an * 8 + ((lane & 3) << 1) + (v & 1);
                        if (rl == cl) e = 0.0f;
                    }
                    rowAcc[am][v >> 1] += e;
                }
        __syncthreads();  // before next B overwrite
    }

    // ---- in-warp reduce (lanes 4k..4k+3 share rows), then atomic
#pragma unroll
    for (int am = 0; am < 2; am++)
#pragma unroll
        for (int h = 0; h < 2; h++) {
            float r = rowAcc[am][h];
            r += __shfl_xor_sync(0xffffffffu, r, 1);
            r += __shfl_xor_sync(0xffffffffu, r, 2);
            if ((lane & 3) == 0) {
                int gr = rowBase + mBase + am * 16 + (lane >> 2) + h * 8;
                atomicAdd(&g_rowsum[gr], r);
            }
        }
}

// ---------------------------------------------------------------- kernel 3
// One warp per pair k: pos dot <zi_k, zj_k> (bf16 inputs, fp32 accumulate).
__global__ __launch_bounds__(256) void pos_kernel() {
    int warpId = threadIdx.x >> 5;
    int lane = threadIdx.x & 31;
    int k = blockIdx.x * 8 + warpId;
    const __nv_bfloat162* a = (const __nv_bfloat162*)(g_Zb + (size_t)k * DDIM);
    const __nv_bfloat162* b = (const __nv_bfloat162*)(g_Zb + (size_t)(k + HALF_N) * DDIM);
    float s = 0.0f;
#pragma unroll
    for (int i = 0; i < 2; i++) {
        __nv_bfloat162 av = a[lane * 2 + i];
        __nv_bfloat162 bv = b[lane * 2 + i];
        s += __bfloat162float(av.x) * __bfloat162float(bv.x);
        s += __bfloat162float(av.y) * __bfloat162float(bv.y);
    }
#pragma unroll
    for (int off = 16; off > 0; off >>= 1)
        s += __shfl_xor_sync(0xffffffffu, s, off);
    if (lane == 0) g_posv[k] = s;
}

// ---------------------------------------------------------------- kernel 4
__global__ __launch_bounds__(256) void finalize_kernel(float* __restrict__ out) {
    __shared__ float red[8];
    int tid = threadIdx.x;
    float local = 0.0f;
    for (int i = tid; i < NTOT; i += 256) local += __logf(g_rowsum[i]);
    for (int i = tid; i < HALF_N; i += 256) local -= 2.0f * INV_T * g_posv[i];
#pragma unroll
    for (int off = 16; off > 0; off >>= 1)
        local += __shfl_xor_sync(0xffffffffu, local, off);
    int lane = tid & 31, warp = tid >> 5;
    if (lane == 0) red[warp] = local;
    __syncthreads();
    if (tid < 8) {
        float v = red[tid];
#pragma unroll
        for (int off = 4; off > 0; off >>= 1)
            v += __shfl_xor_sync(0xffu, v, off);
        if (tid == 0) out[0] = v / (float)NTOT;
    }
}

// ---------------------------------------------------------------- launch
extern "C" void kernel_launch(void* const* d_in, const int* in_sizes, int n_in,
                              void* d_out, int out_size) {
    const float* zi = (const float*)d_in[0];
    const float* zj = (const float*)d_in[1];
    float* out = (float*)d_out;

    norm_kernel<<<NTOT / 8, 256>>>(zi, zj);
    simlse_kernel<<<dim3(64, 8), 256>>>();
    pos_kernel<<<HALF_N / 8, 256>>>();
    finalize_kernel<<<1, 256>>>(out);
}

// round 3
// speedup vs baseline: 1.9912x; 1.9912x over previous
#include <cuda_runtime.h>
#include <cuda_bf16.h>
#include <cstdint>

// NT-Xent loss. Arch-guarded: tcgen05 body on sm_103a pass, mma.sync fallback
// on the plain sm_103 pass (ptxas rejects tcgen05 without the 'a' target).

#define NTOT 8192
#define HALF_N 4096
#define DDIM 128
#define SCALE_EX2 20.6099291555566218f   // log2(e)/0.07
#define INV_T (1.0f/0.07f)

#if defined(__CUDA_ARCH__) && (defined(__CUDA_ARCH_FEAT_SM103_ALL) || defined(__CUDA_ARCH_SPECIFIC__))
#define HAS_TCGEN05 1
#else
#define HAS_TCGEN05 0
#endif

__device__ __nv_bfloat16 g_Zb[NTOT * DDIM];
__device__ float g_rowsum[NTOT];
__device__ float g_posv[HALF_N];
__device__ float g_accum;
__device__ int   g_cnt;

// ---------------------------------------------------------------- common utils
__device__ __forceinline__ float fexp2(float x) {
    float y;
    asm("ex2.approx.f32 %0, %1;" : "=f"(y) : "f"(x));
    return y;
}
__device__ __forceinline__ void cp_async16(uint32_t dst, const void* src) {
    asm volatile("cp.async.cg.shared.global [%0], [%1], 16;"
                 :: "r"(dst), "l"(src) : "memory");
}
__device__ __forceinline__ void cp_commit() {
    asm volatile("cp.async.commit_group;" ::: "memory");
}
template <int N>
__device__ __forceinline__ void cp_wait() {
    asm volatile("cp.async.wait_group %0;" :: "n"(N) : "memory");
}

// ---------------------------------------------------------------- kernel 1
__global__ __launch_bounds__(256) void norm_kernel(const float* __restrict__ zi,
                                                   const float* __restrict__ zj) {
    int warpId = threadIdx.x >> 5;
    int lane = threadIdx.x & 31;
    int row = blockIdx.x * 8 + warpId;
    const float* src = (row < HALF_N) ? (zi + (size_t)row * DDIM)
                                      : (zj + (size_t)(row - HALF_N) * DDIM);
    float4 v = ((const float4*)src)[lane];
    float ss = v.x * v.x + v.y * v.y + v.z * v.z + v.w * v.w;
#pragma unroll
    for (int off = 16; off > 0; off >>= 1)
        ss += __shfl_xor_sync(0xffffffffu, ss, off);
    float s = rsqrtf(fmaxf(ss, 1e-24f));
    __nv_bfloat162 h0 = __floats2bfloat162_rn(v.x * s, v.y * s);
    __nv_bfloat162 h1 = __floats2bfloat162_rn(v.z * s, v.w * s);
    __nv_bfloat162* dst = (__nv_bfloat162*)(g_Zb + (size_t)row * DDIM);
    dst[lane * 2 + 0] = h0;
    dst[lane * 2 + 1] = h1;
    if (lane == 0) g_rowsum[row] = 0.0f;
    if (blockIdx.x == 0 && threadIdx.x == 0) { g_accum = 0.0f; g_cnt = 0; }
}

// ---------------------------------------------------------------- kernel 2
// Unified config for both arch bodies: grid(64,8), 256 threads, dynamic smem.
#define SM_A    0
#define SM_B0   32768
#define SM_B1   65536
#define SM_CTRL 98304
#define SMEM_REQ (98368 + 1024)

#if HAS_TCGEN05
// ---------------- tcgen05 helpers (sm_103a pass only) ----------------
__device__ __forceinline__ uint32_t elect_one() {
    uint32_t p;
    asm volatile("{\n\t.reg .pred p;\n\telect.sync _|p, 0xFFFFFFFF;\n\t"
                 "selp.b32 %0, 1, 0, p;\n\t}" : "=r"(p));
    return p;
}
__device__ __forceinline__ void mbar_init(uint32_t a, uint32_t cnt) {
    asm volatile("mbarrier.init.shared.b64 [%0], %1;" :: "r"(a), "r"(cnt) : "memory");
}
__device__ __forceinline__ void mbar_inval(uint32_t a) {
    asm volatile("mbarrier.inval.shared.b64 [%0];" :: "r"(a) : "memory");
}
__device__ __forceinline__ void mbar_wait(uint32_t a, uint32_t phase) {
    asm volatile(
        "{\n\t.reg .pred P;\n\t"
        "W%=:\n\t"
        "mbarrier.try_wait.parity.acquire.cta.shared::cta.b64 P, [%0], %1, 0x989680;\n\t"
        "@P bra D%=;\n\t"
        "bra W%=;\n\t"
        "D%=:\n\t}"
        :: "r"(a), "r"(phase) : "memory");
}
__device__ __forceinline__ void tc_alloc(uint32_t smem_res, uint32_t ncols) {
    asm volatile("tcgen05.alloc.cta_group::1.sync.aligned.shared::cta.b32 [%0], %1;"
                 :: "r"(smem_res), "r"(ncols) : "memory");
}
__device__ __forceinline__ void tc_dealloc(uint32_t tmem, uint32_t ncols) {
    asm volatile("tcgen05.dealloc.cta_group::1.sync.aligned.b32 %0, %1;"
                 :: "r"(tmem), "r"(ncols));
}
__device__ __forceinline__ void tc_commit(uint32_t mbar) {
    asm volatile("tcgen05.commit.cta_group::1.mbarrier::arrive::one.shared::cluster.b64 [%0];"
                 :: "r"(mbar) : "memory");
}
__device__ __forceinline__ void tc_fence_before() {
    asm volatile("tcgen05.fence::before_thread_sync;" ::: "memory");
}
__device__ __forceinline__ void tc_fence_after() {
    asm volatile("tcgen05.fence::after_thread_sync;" ::: "memory");
}
__device__ __forceinline__ void tc_wait_ld() {
    asm volatile("tcgen05.wait::ld.sync.aligned;" ::: "memory");
}
__device__ __forceinline__ void fence_proxy_async_cta() {
    asm volatile("fence.proxy.async.shared::cta;" ::: "memory");
}
__device__ __forceinline__ void tc_mma_f16_ss(uint32_t d, uint64_t ad, uint64_t bd,
                                              uint32_t idesc, uint32_t en) {
    asm volatile(
        "{\n\t.reg .pred p;\n\tsetp.ne.u32 p, %4, 0;\n\t"
        "tcgen05.mma.cta_group::1.kind::f16 [%0], %1, %2, %3, {%5, %5, %5, %5}, p;\n\t}"
        :: "r"(d), "l"(ad), "l"(bd), "r"(idesc), "r"(en), "r"(0u) : "memory");
}
__device__ __forceinline__ void tc_ld_x32(uint32_t* r, uint32_t a) {
    asm volatile(
        "tcgen05.ld.sync.aligned.32x32b.x32.b32 "
        "{%0,%1,%2,%3,%4,%5,%6,%7,%8,%9,%10,%11,%12,%13,%14,%15,"
        "%16,%17,%18,%19,%20,%21,%22,%23,%24,%25,%26,%27,%28,%29,%30,%31}, [%32];"
        : "=r"(r[0]), "=r"(r[1]), "=r"(r[2]), "=r"(r[3]), "=r"(r[4]), "=r"(r[5]),
          "=r"(r[6]), "=r"(r[7]), "=r"(r[8]), "=r"(r[9]), "=r"(r[10]), "=r"(r[11]),
          "=r"(r[12]), "=r"(r[13]), "=r"(r[14]), "=r"(r[15]), "=r"(r[16]), "=r"(r[17]),
          "=r"(r[18]), "=r"(r[19]), "=r"(r[20]), "=r"(r[21]), "=r"(r[22]), "=r"(r[23]),
          "=r"(r[24]), "=r"(r[25]), "=r"(r[26]), "=r"(r[27]), "=r"(r[28]), "=r"(r[29]),
          "=r"(r[30]), "=r"(r[31])
        : "r"(a));
}
// SMEM desc: SW128, version 1 (Blackwell), SBO=64, LBO=1 (K-major)
static __device__ __forceinline__ uint64_t mk_desc(uint32_t addr) {
    return (2ull << 61) | (1ull << 46) | (64ull << 32) | (1ull << 16) |
           ((uint64_t)(addr >> 4) & 0x3FFF);
}
// idesc: F32 accum, bf16 a/b, M=128, N=128
#define IDESC ((1u << 4) | (1u << 7) | (1u << 10) | (16u << 17) | (8u << 24))

// 128x128 bf16 tile -> SW128 blocked-atom layout (atom-col stride 16 KB)
__device__ __forceinline__ void copy_tile(uint32_t sm_dst, int gRow0, int tid) {
    const char* gbase = (const char*)g_Zb + (size_t)gRow0 * DDIM * 2;
#pragma unroll
    for (int i = 0; i < 8; i++) {
        int idx = i * 256 + tid;
        int r = idx >> 4, c = idx & 15;
        uint32_t off = (uint32_t)(r * 128 + (c & 7) * 16);
        uint32_t dst = sm_dst + (uint32_t)((c >> 3) * 16384) +
                       (off ^ ((off >> 3) & 0x70));
        cp_async16(dst, gbase + r * 256 + c * 16);
    }
}
#endif  // HAS_TCGEN05

#if !HAS_TCGEN05
// ---------------- mma.sync fallback helpers ----------------
#define PAD 136
__device__ __forceinline__ void ldmatrix_x4(uint32_t* r, const void* p) {
    uint32_t sa = (uint32_t)__cvta_generic_to_shared(p);
    asm volatile("ldmatrix.sync.aligned.m8n8.x4.shared.b16 {%0,%1,%2,%3}, [%4];"
                 : "=r"(r[0]), "=r"(r[1]), "=r"(r[2]), "=r"(r[3]) : "r"(sa));
}
__device__ __forceinline__ void mma16816(float* d, const uint32_t* a,
                                          uint32_t b0, uint32_t b1) {
    asm volatile(
        "mma.sync.aligned.m16n8k16.row.col.f32.bf16.bf16.f32 "
        "{%0,%1,%2,%3}, {%4,%5,%6,%7}, {%8,%9}, {%0,%1,%2,%3};"
        : "+f"(d[0]), "+f"(d[1]), "+f"(d[2]), "+f"(d[3])
        : "r"(a[0]), "r"(a[1]), "r"(a[2]), "r"(a[3]), "r"(b0), "r"(b1));
}
#endif

__global__ void __launch_bounds__(256, 2) simlse_tc() {
    extern __shared__ char dsm[];
    int tid = threadIdx.x;
    int lane = tid & 31;
    int wid = tid >> 5;
    int rowBase = blockIdx.x * 128;

#if HAS_TCGEN05
    // ================= tcgen05 body =================
    uint32_t raw = (uint32_t)__cvta_generic_to_shared(dsm);
    uint32_t base = (raw + 1023u) & ~1023u;
    int colTile0 = blockIdx.y * 8;

    if (wid == 0) tc_alloc(base + SM_CTRL, 256);
    if (tid == 0) { mbar_init(base + SM_CTRL + 8, 1); mbar_init(base + SM_CTRL + 16, 1); }
    __syncthreads();
    uint32_t tmem;
    asm volatile("ld.shared.b32 %0, [%1];" : "=r"(tmem) : "r"(base + SM_CTRL));

    copy_tile(base + SM_A, rowBase, tid);
    copy_tile(base + SM_B0, colTile0 * 128, tid);
    cp_commit();

    uint64_t descA = mk_desc(base + SM_A);
    const uint32_t kOff[8] = {0, 2, 4, 6, 1024, 1026, 1028, 1030};

    uint32_t phase0 = 0, phase1 = 0;
    float rowAcc = 0.0f;
    int myRow = rowBase + (wid & 3) * 32 + lane;
    uint32_t tsub = ((uint32_t)(wid & 3)) << 21;
    int colHalf = (wid >> 2) * 64;

    for (int t = 0; t < 8; t++) {
        int buf = t & 1;
        if (t > 0) {
            int pb = (t - 1) & 1;
            mbar_wait(base + SM_CTRL + 8 + 8 * pb, pb ? phase1 : phase0);
            if (pb) phase1 ^= 1; else phase0 ^= 1;
            tc_fence_after();
        }
        if (t < 7) {
            copy_tile(base + (((t + 1) & 1) ? SM_B1 : SM_B0), (colTile0 + t + 1) * 128, tid);
            cp_commit();
            cp_wait<1>();
        } else {
            cp_wait<0>();
        }
        fence_proxy_async_cta();
        __syncthreads();
        if (wid == 0 && elect_one()) {
            uint64_t descB = mk_desc(base + (buf ? SM_B1 : SM_B0));
            uint32_t dAddr = tmem + buf * 128;
#pragma unroll
            for (int ks = 0; ks < 8; ks++)
                tc_mma_f16_ss(dAddr, descA + kOff[ks], descB + kOff[ks], IDESC, ks > 0);
            tc_commit(base + SM_CTRL + 8 + 8 * buf);
        }
        if (t > 0) {
            int pt = t - 1;
            int colBase = (colTile0 + pt) * 128;
            uint32_t dAddr = tmem + (pt & 1) * 128 + tsub + colHalf;
            uint32_t r0[32], r1[32];
            tc_ld_x32(r0, dAddr);
            tc_ld_x32(r1, dAddr + 32);
            tc_wait_ld();
            int gc0 = colBase + colHalf;
            if (rowBase == colBase) {
#pragma unroll
                for (int c = 0; c < 32; c++) {
                    float e0 = fexp2(__uint_as_float(r0[c]) * SCALE_EX2);
                    float e1 = fexp2(__uint_as_float(r1[c]) * SCALE_EX2);
                    if (gc0 + c == myRow) e0 = 0.0f;
                    if (gc0 + 32 + c == myRow) e1 = 0.0f;
                    rowAcc += e0 + e1;
                }
            } else {
#pragma unroll
                for (int c = 0; c < 32; c++)
                    rowAcc += fexp2(__uint_as_float(r0[c]) * SCALE_EX2) +
                              fexp2(__uint_as_float(r1[c]) * SCALE_EX2);
            }
            tc_fence_before();
        }
    }
    {
        mbar_wait(base + SM_CTRL + 16, phase1);
        tc_fence_after();
        int colBase = (colTile0 + 7) * 128;
        uint32_t dAddr = tmem + 128 + tsub + colHalf;
        uint32_t r0[32], r1[32];
        tc_ld_x32(r0, dAddr);
        tc_ld_x32(r1, dAddr + 32);
        tc_wait_ld();
        int gc0 = colBase + colHalf;
        if (rowBase == colBase) {
#pragma unroll
            for (int c = 0; c < 32; c++) {
                float e0 = fexp2(__uint_as_float(r0[c]) * SCALE_EX2);
                float e1 = fexp2(__uint_as_float(r1[c]) * SCALE_EX2);
                if (gc0 + c == myRow) e0 = 0.0f;
                if (gc0 + 32 + c == myRow) e1 = 0.0f;
                rowAcc += e0 + e1;
            }
        } else {
#pragma unroll
            for (int c = 0; c < 32; c++)
                rowAcc += fexp2(__uint_as_float(r0[c]) * SCALE_EX2) +
                          fexp2(__uint_as_float(r1[c]) * SCALE_EX2);
        }
        tc_fence_before();
    }

    atomicAdd(&g_rowsum[myRow], rowAcc);

    __syncthreads();
    if (tid == 0) { mbar_inval(base + SM_CTRL + 8); mbar_inval(base + SM_CTRL + 16); }
    __syncthreads();
    if (wid == 0) tc_dealloc(tmem, 256);

#else
    // ================= mma.sync fallback body =================
    __nv_bfloat16* sT = (__nv_bfloat16*)dsm;
    int warpM = wid & 3;
    int warpN = wid >> 2;
    int mBase = warpM * 32;
    int nBase = warpN * 64;

    {
        const int4* src = (const int4*)(g_Zb + (size_t)rowBase * DDIM);
#pragma unroll
        for (int i = 0; i < 8; i++) {
            int idx = i * 256 + tid;
            int r = idx >> 4, c = idx & 15;
            *(int4*)(&sT[r * PAD + c * 8]) = src[r * 16 + c];
        }
    }
    __syncthreads();

    uint32_t aF[8][2][4];
#pragma unroll
    for (int ks = 0; ks < 8; ks++)
#pragma unroll
        for (int am = 0; am < 2; am++) {
            const __nv_bfloat16* p =
                &sT[(mBase + am * 16 + (lane & 15)) * PAD + ks * 16 + (lane >> 4) * 8];
            ldmatrix_x4(aF[ks][am], p);
        }
    __syncthreads();

    float rowAcc[2][2] = {{0.f, 0.f}, {0.f, 0.f}};

    for (int ct = 0; ct < 8; ct++) {
        int colBase = blockIdx.y * 1024 + ct * 128;
        {
            const int4* src = (const int4*)(g_Zb + (size_t)colBase * DDIM);
#pragma unroll
            for (int i = 0; i < 8; i++) {
                int idx = i * 256 + tid;
                int r = idx >> 4, c = idx & 15;
                *(int4*)(&sT[r * PAD + c * 8]) = src[r * 16 + c];
            }
        }
        __syncthreads();

        float acc[2][8][4];
#pragma unroll
        for (int am = 0; am < 2; am++)
#pragma unroll
            for (int an = 0; an < 8; an++)
#pragma unroll
                for (int v = 0; v < 4; v++) acc[am][an][v] = 0.0f;

#pragma unroll
        for (int ks = 0; ks < 8; ks++) {
            uint32_t bF[4][4];
#pragma unroll
            for (int bn = 0; bn < 4; bn++) {
                const __nv_bfloat16* p =
                    &sT[(nBase + bn * 16 + (lane & 15)) * PAD + ks * 16 + (lane >> 4) * 8];
                ldmatrix_x4(bF[bn], p);
            }
#pragma unroll
            for (int am = 0; am < 2; am++)
#pragma unroll
                for (int an = 0; an < 8; an++) {
                    uint32_t b0 = bF[an >> 1][(an & 1)];
                    uint32_t b1 = bF[an >> 1][2 + (an & 1)];
                    mma16816(acc[am][an], aF[ks][am], b0, b1);
                }
        }

        bool diag = (rowBase == colBase);
#pragma unroll
        for (int am = 0; am < 2; am++)
#pragma unroll
            for (int an = 0; an < 8; an++)
#pragma unroll
                for (int v = 0; v < 4; v++) {
                    float e = fexp2(acc[am][an][v] * SCALE_EX2);
                    if (diag) {
                        int rl = mBase + am * 16 + (lane >> 2) + ((v >> 1) << 3);
                        int cl = nBase + an * 8 + ((lane & 3) << 1) + (v & 1);
                        if (rl == cl) e = 0.0f;
                    }
                    rowAcc[am][v >> 1] += e;
                }
        __syncthreads();
    }

#pragma unroll
    for (int am = 0; am < 2; am++)
#pragma unroll
        for (int h = 0; h < 2; h++) {
            float r = rowAcc[am][h];
            r += __shfl_xor_sync(0xffffffffu, r, 1);
            r += __shfl_xor_sync(0xffffffffu, r, 2);
            if ((lane & 3) == 0) {
                int gr = rowBase + mBase + am * 16 + (lane >> 2) + h * 8;
                atomicAdd(&g_rowsum[gr], r);
            }
        }
#endif
}

// ---------------------------------------------------------------- kernel 3
__global__ __launch_bounds__(256) void pos_kernel() {
    int warpId = threadIdx.x >> 5;
    int lane = threadIdx.x & 31;
    int k = blockIdx.x * 8 + warpId;
    const __nv_bfloat162* a = (const __nv_bfloat162*)(g_Zb + (size_t)k * DDIM);
    const __nv_bfloat162* b = (const __nv_bfloat162*)(g_Zb + (size_t)(k + HALF_N) * DDIM);
    float s = 0.0f;
#pragma unroll
    for (int i = 0; i < 2; i++) {
        __nv_bfloat162 av = a[lane * 2 + i];
        __nv_bfloat162 bv = b[lane * 2 + i];
        s += __bfloat162float(av.x) * __bfloat162float(bv.x);
        s += __bfloat162float(av.y) * __bfloat162float(bv.y);
    }
#pragma unroll
    for (int off = 16; off > 0; off >>= 1)
        s += __shfl_xor_sync(0xffffffffu, s, off);
    if (lane == 0) g_posv[k] = s;
}

// ---------------------------------------------------------------- kernel 4
__global__ __launch_bounds__(256) void finalize_kernel(float* __restrict__ out) {
    __shared__ float red[8];
    int tid = threadIdx.x;
    int i = blockIdx.x * 256 + tid;
    float v = __logf(g_rowsum[i]);
    if (i < HALF_N) v -= 2.0f * INV_T * g_posv[i];
#pragma unroll
    for (int off = 16; off > 0; off >>= 1)
        v += __shfl_xor_sync(0xffffffffu, v, off);
    int lane = tid & 31, warp = tid >> 5;
    if (lane == 0) red[warp] = v;
    __syncthreads();
    if (tid == 0) {
        float b = 0.0f;
#pragma unroll
        for (int w = 0; w < 8; w++) b += red[w];
        atomicAdd(&g_accum, b);
        __threadfence();
        int old = atomicAdd(&g_cnt, 1);
        if (old == 31)
            out[0] = atomicAdd(&g_accum, 0.0f) * (1.0f / (float)NTOT);
    }
}

// ---------------------------------------------------------------- launch
extern "C" void kernel_launch(void* const* d_in, const int* in_sizes, int n_in,
                              void* d_out, int out_size) {
    const float* zi = (const float*)d_in[0];
    const float* zj = (const float*)d_in[1];
    float* out = (float*)d_out;

    static int smem_set = 0;
    if (!smem_set) {
        cudaFuncSetAttribute(simlse_tc, cudaFuncAttributeMaxDynamicSharedMemorySize,
                             SMEM_REQ);
        smem_set = 1;
    }

    norm_kernel<<<NTOT / 8, 256>>>(zi, zj);
    simlse_tc<<<dim3(64, 8), 256, SMEM_REQ>>>();
    pos_kernel<<<HALF_N / 8, 256>>>();
    finalize_kernel<<<32, 256>>>(out);
}